// round 15
// baseline (speedup 1.0000x reference)
#include <cuda_runtime.h>
#include <cuda_bf16.h>
#include <cstdint>

// Problem constants (V=250000, H=128, N=32768, K=256).
#define HD      128
#define KS      256
#define THREADS 256
#define GRID    256              // each CTA owns 128 contiguous rows (2 x 64-row tiles)
#define LDBE    136              // padded row stride (bf16 elems): conflict-free ldmatrix
#define ROWB    (LDBE * 2)       // 272 bytes per row

// exp(2x) = 2^(K2E * x);  shift C=12 keeps args in [-30, +30] (outputs ~ [7,19]).
#define K2E  2.885390081777927f          // 2 * log2(e)
#define CSH  12.0f
#define TC   (CSH * K2E)                 // 34.6246809813...

// ---------------- smem layout (bytes) ----------------
#define OFF_B    0                        // B image 256 x 136 bf16   (69632 B)
#define OFF_A    69632                    // A image 128 x 136 bf16   (34816 B)
#define OFF_CBE  104448                   // float[256]  (cb - 12) * K2E
#define OFF_TIDX 105472                   // int[128]   target indices
#define OFF_TL   105984                   // float[128] target logits
#define OFF_RS   106496                   // float[64*4] per-(row,ngroup) sumexp
#define OFF_RED  107520                   // float[256]
#define OFF_WRD  108544                   // float[2]
#define OFF_LAST 108552                   // int
#define SMEM_TOTAL 108576                 // x2 CTAs = 217 KB < 228 KB/SM

// ---------------- device globals (no allocation allowed) ----------------
__device__ float        g_partials[GRID];
__device__ unsigned int g_done;

// ---------------- helpers ----------------
__device__ __forceinline__ uint32_t smem_u32(const void* p) {
    uint32_t a;
    asm("{ .reg .u64 t; cvta.to.shared.u64 t, %1; cvt.u32.u64 %0, t; }" : "=r"(a) : "l"(p));
    return a;
}
__device__ __forceinline__ unsigned pk(float lo, float hi) {
    __nv_bfloat162 t = __floats2bfloat162_rn(lo, hi);
    return *reinterpret_cast<unsigned*>(&t);
}
#define LDSM4(r, a) \
    asm volatile("ldmatrix.sync.aligned.m8n8.x4.shared.b16 {%0,%1,%2,%3}, [%4];" \
        : "=r"((r)[0]), "=r"((r)[1]), "=r"((r)[2]), "=r"((r)[3]) : "r"(a))
__device__ __forceinline__ void mma_bf16(float* d, const uint32_t* a,
                                         uint32_t b0, uint32_t b1) {
    asm volatile("mma.sync.aligned.m16n8k16.row.col.f32.bf16.bf16.f32 "
                 "{%0,%1,%2,%3}, {%4,%5,%6,%7}, {%8,%9}, {%0,%1,%2,%3};"
                 : "+f"(d[0]), "+f"(d[1]), "+f"(d[2]), "+f"(d[3])
                 : "r"(a[0]), "r"(a[1]), "r"(a[2]), "r"(a[3]), "r"(b0), "r"(b1));
}

// int64-vs-int32 detection: int64 indices (<2^32) have all hi-words zero.
__device__ __forceinline__ int detect64(const void* idx, int lane) {
    unsigned hi = ((const unsigned*)idx)[2 * lane + 1];
    return __all_sync(0xffffffffu, hi == 0u);
}

// ---------------- single fused kernel: 2 CTAs/SM, 128 rows/CTA, 1 wave ----
__global__ __launch_bounds__(THREADS, 2)
void k_all(const float* __restrict__ weight, const float* __restrict__ bias,
           const float* __restrict__ hiddens, const float* __restrict__ nl,
           const void* __restrict__ targets, const void* __restrict__ samples,
           float* __restrict__ out, int N) {
    extern __shared__ __align__(16) char smem[];
    const int tid = threadIdx.x, w = tid >> 5, lane = tid & 31;
    const int row0 = blockIdx.x << 7;             // 128 rows per CTA
    const uint32_t sb = smem_u32(smem);
    float* cbE  = (float*)(smem + OFF_CBE);
    int*   tIdx = (int*)(smem + OFF_TIDX);
    float* tl   = (float*)(smem + OFF_TL);
    float* rs   = (float*)(smem + OFF_RS);
    float* red  = (float*)(smem + OFF_RED);
    float* wrd  = (float*)(smem + OFF_WRD);
    int*   last = (int*)(smem + OFF_LAST);

    const int is64_t = detect64(targets, lane);   // warp-uniform
    const int is64_s = detect64(samples, lane);

    // ---------- Phase 1: one max-MLP load burst, one barrier ----------
    if (tid < 128) {
        long long t = is64_t ? ((const long long*)targets)[row0 + tid]
                             : (long long)((const int*)targets)[row0 + tid];
        tIdx[tid] = (int)t;
    }
    // A fill: 128 rows fp32 hiddens -> bf16 padded image.
#pragma unroll
    for (int it = 0; it < 16; it++) {
        int i = tid + it * THREADS;               // 4096 float4 chunks
        int r = i >> 5, c4 = i & 31;
        float4 v = ((const float4*)hiddens)[((size_t)(row0 + r)) * 32 + c4];
        *(uint2*)(smem + OFF_A + r * ROWB + c4 * 8) =
            make_uint2(pk(v.x, v.y), pk(v.z, v.w));
    }
    // B fill: gather sample weight rows -> bf16 padded image (L2-hot).
    for (int i = tid; i < KS * HD / 8; i += THREADS) {  // 4096 chunks of 8 elems
        int n = i >> 4, c = i & 15;
        long long s = is64_s ? ((const long long*)samples)[n]
                             : (long long)((const int*)samples)[n];
        const float4* wr = (const float4*)(weight + (size_t)s * HD);
        float4 a = wr[c * 2], b = wr[c * 2 + 1];
        *(uint4*)(smem + OFF_B + n * ROWB + c * 16) =
            make_uint4(pk(a.x, a.y), pk(a.z, a.w), pk(b.x, b.y), pk(b.z, b.w));
    }
    {
        long long s = is64_s ? ((const long long*)samples)[tid]
                             : (long long)((const int*)samples)[tid];
        cbE[tid] = (bias[s] - nl[s] - CSH) * K2E;
    }
    if (tid == 0) *last = 0;
    __syncthreads();

    // ---------- Phase 2: target logits from smem bf16 A + batched gathers ----
#pragma unroll
    for (int b = 0; b < 2; b++) {
        int tt[8]; float4 wv[8]; uint2 hv[8]; float bn_[8];
#pragma unroll
        for (int j = 0; j < 8; j++) tt[j] = tIdx[w * 16 + b * 8 + j];
#pragma unroll
        for (int j = 0; j < 8; j++)
            wv[j] = ((const float4*)weight)[(size_t)tt[j] * 32 + lane];
#pragma unroll
        for (int j = 0; j < 8; j++) {
            int m = w * 16 + b * 8 + j;
            hv[j] = *(const uint2*)(smem + OFF_A + m * ROWB + lane * 8);
        }
#pragma unroll
        for (int j = 0; j < 8; j++) bn_[j] = __ldg(bias + tt[j]) - __ldg(nl + tt[j]);
#pragma unroll
        for (int j = 0; j < 8; j++) {
            __nv_bfloat162 h0 = *reinterpret_cast<__nv_bfloat162*>(&hv[j].x);
            __nv_bfloat162 h1 = *reinterpret_cast<__nv_bfloat162*>(&hv[j].y);
            float d = __bfloat162float(h0.x) * wv[j].x + __bfloat162float(h0.y) * wv[j].y
                    + __bfloat162float(h1.x) * wv[j].z + __bfloat162float(h1.y) * wv[j].w;
#pragma unroll
            for (int o = 16; o; o >>= 1) d += __shfl_xor_sync(0xffffffffu, d, o);
            if (lane == 0) tl[w * 16 + b * 8 + j] = d + bn_[j];
        }
    }
    // tl consumed only after the epilogue barrier below.

    // ---------- Phase 3: two DRAM-free MMA + sumexp passes (no max pass) ----
    float cta_part = 0.f;
    const int bm = (w & 1) * 32, bn = (w >> 1) * 64;
#pragma unroll
    for (int t = 0; t < 2; t++) {
        float d[2][8][4];
#pragma unroll
        for (int mf = 0; mf < 2; mf++)
#pragma unroll
            for (int nf = 0; nf < 8; nf++)
#pragma unroll
                for (int q = 0; q < 4; q++) d[mf][nf][q] = 0.f;

        const uint32_t aB = sb + OFF_A + (t * 64 + bm + (lane & 15)) * ROWB
                          + ((lane >> 4) << 4);
        const uint32_t bB = sb + OFF_B + (bn + (lane & 15)) * ROWB
                          + ((lane >> 4) << 4);
#pragma unroll
        for (int ks = 0; ks < 8; ks++) {
            const uint32_t off = ks * 32;
            uint32_t a[2][4], bb[4][4];
            LDSM4(a[0], aB + off);
            LDSM4(a[1], aB + 16 * ROWB + off);
#pragma unroll
            for (int q = 0; q < 4; q++) LDSM4(bb[q], bB + q * 16 * ROWB + off);
#pragma unroll
            for (int mf = 0; mf < 2; mf++)
#pragma unroll
                for (int nf = 0; nf < 8; nf++)
                    mma_bf16(d[mf][nf], a[mf], bb[nf >> 1][nf & 1],
                             bb[nf >> 1][(nf & 1) + 2]);
        }

        // Epilogue: per-row sum of exp2(K2E*d + cbE) over this warp's 64 cols.
        const int g = lane >> 2, t4 = lane & 3;
        float2 cbl[8];
#pragma unroll
        for (int nf = 0; nf < 8; nf++)
            cbl[nf] = *(const float2*)&cbE[bn + nf * 8 + t4 * 2];
#pragma unroll
        for (int mf = 0; mf < 2; mf++)
#pragma unroll
            for (int h = 0; h < 2; h++) {
                int row = bm + mf * 16 + h * 8 + g;
                float s = 0.f;
#pragma unroll
                for (int nf = 0; nf < 8; nf++) {
                    s += exp2f(fmaf(d[mf][nf][h * 2],     K2E, cbl[nf].x));
                    s += exp2f(fmaf(d[mf][nf][h * 2 + 1], K2E, cbl[nf].y));
                }
                s += __shfl_xor_sync(0xffffffffu, s, 1);
                s += __shfl_xor_sync(0xffffffffu, s, 2);
                if (t4 == 0) rs[row * 4 + (w >> 1)] = s;
            }
        __syncthreads();

        // Merge 4 n-group partials + target column per row; fixed-order reduce.
        if (w < 2) {
            int row = w * 32 + lane;
            float tv = tl[t * 64 + row];
            float S = rs[row * 4] + rs[row * 4 + 1] + rs[row * 4 + 2] + rs[row * 4 + 3]
                    + exp2f(fmaf(tv, K2E, -TC));
            float res = tv - CSH - 0.5f * logf(S);
#pragma unroll
            for (int o = 16; o; o >>= 1) res += __shfl_xor_sync(0xffffffffu, res, o);
            if (lane == 0) wrd[w] = res;
        }
        __syncthreads();
        if (tid == 0) cta_part += wrd[0] + wrd[1];
        // tid0's read is ordered before the next tile's wrd write by the next
        // epilogue/merge barriers in which tid0 participates.
    }

    // ---------- completion counter + deterministic final reduction ----------
    if (tid == 0) {
        g_partials[blockIdx.x] = cta_part;
        __threadfence();
        unsigned prev = atomicAdd(&g_done, 1u);
        *last = (prev == GRID - 1) ? 1 : 0;
    }
    __syncthreads();
    if (*last) {
        __threadfence();
        red[tid] = g_partials[tid];
        __syncthreads();
#pragma unroll
        for (int s = 128; s > 0; s >>= 1) {
            if (tid < s) red[tid] += red[tid + s];
            __syncthreads();
        }
        if (tid == 0) { out[0] = -red[0] / (float)N; g_done = 0u; }
    }
}

extern "C" void kernel_launch(void* const* d_in, const int* in_sizes, int n_in,
                              void* d_out, int out_size) {
    const float* weight  = (const float*)d_in[0];
    const float* bias    = (const float*)d_in[1];
    const float* hiddens = (const float*)d_in[2];
    const float* nl      = (const float*)d_in[3];
    const void*  targets = d_in[4];
    const void*  samples = d_in[5];
    (void)n_in; (void)out_size;

    const int N = in_sizes[4];          // 32768 -> 256 CTAs x 128 rows

    cudaFuncSetAttribute(k_all, cudaFuncAttributeMaxDynamicSharedMemorySize, SMEM_TOTAL);

    k_all<<<N / 128, THREADS, SMEM_TOTAL>>>(weight, bias, hiddens, nl, targets, samples,
                                            (float*)d_out, N);
}

// round 16
// speedup vs baseline: 1.1684x; 1.1684x over previous
#include <cuda_runtime.h>
#include <cuda_bf16.h>
#include <cstdint>

// Problem constants (V=250000, H=128, N=32768, K=256).
#define HD      128
#define KS      256
#define THREADS 256
#define GRID    256              // each CTA owns 128 contiguous rows (2 x 64-row tiles)
#define ROWB    144              // padded row stride bytes (128 e4m3 + 16 pad): 16B-aligned,
                                 // phase(r) = 9r mod 8 = r mod 8 -> conflict-free ldmatrix

// exp(2x) = 2^(K2E * x); B is scaled x16 so accum d = 16*logit -> multiplier K2E/16.
#define K2E    2.885390081777927f        // 2 * log2(e)
#define K2E16  0.1803368801111204f       // K2E / 16
#define CSH    12.0f                     // shift keeping exp2 args in +-30
#define TC     (CSH * K2E)

// ---------------- smem layout (bytes) ----------------
#define OFF_B    0                        // B image 256 x 144 e4m3  (36864 B)
#define OFF_A    36864                    // A image 128 x 144 e4m3  (18432 B)
#define OFF_CBE  55296                    // float[256]  (bias-nl-CSH)*K2E
#define OFF_TIDX 56320                    // int[128]
#define OFF_TL   56832                    // float[128]
#define OFF_RS   57344                    // float[64*4]
#define OFF_RED  58368                    // float[256]
#define OFF_WRD  59392                    // float[2]
#define OFF_LAST 59400                    // int
#define SMEM_TOTAL 59424                  // x2 CTAs = 119 KB < 228 KB/SM

// ---------------- device globals (no allocation allowed) ----------------
__device__ float        g_partials[GRID];
__device__ unsigned int g_done;

// ---------------- helpers ----------------
__device__ __forceinline__ uint32_t smem_u32(const void* p) {
    uint32_t a;
    asm("{ .reg .u64 t; cvta.to.shared.u64 t, %1; cvt.u32.u64 %0, t; }" : "=r"(a) : "l"(p));
    return a;
}
// Pack two floats into two e4m3 bytes (lo in low byte).
__device__ __forceinline__ unsigned short pk8(float lo, float hi) {
    unsigned short r;
    asm("cvt.rn.satfinite.e4m3x2.f32 %0, %1, %2;" : "=h"(r) : "f"(hi), "f"(lo));
    return r;
}
#define LDSM4(r, a) \
    asm volatile("ldmatrix.sync.aligned.m8n8.x4.shared.b16 {%0,%1,%2,%3}, [%4];" \
        : "=r"((r)[0]), "=r"((r)[1]), "=r"((r)[2]), "=r"((r)[3]) : "r"(a))
__device__ __forceinline__ void mma_fp8(float* d, const uint32_t* a,
                                        uint32_t b0, uint32_t b1) {
    asm volatile("mma.sync.aligned.m16n8k32.row.col.f32.e4m3.e4m3.f32 "
                 "{%0,%1,%2,%3}, {%4,%5,%6,%7}, {%8,%9}, {%0,%1,%2,%3};"
                 : "+f"(d[0]), "+f"(d[1]), "+f"(d[2]), "+f"(d[3])
                 : "r"(a[0]), "r"(a[1]), "r"(a[2]), "r"(a[3]), "r"(b0), "r"(b1));
}

// int64-vs-int32 detection: int64 indices (<2^32) have all hi-words zero.
__device__ __forceinline__ int detect64(const void* idx, int lane) {
    unsigned hi = ((const unsigned*)idx)[2 * lane + 1];
    return __all_sync(0xffffffffu, hi == 0u);
}

// ---------------- single fused kernel: 2 CTAs/SM, 128 rows/CTA, 1 wave ----
__global__ __launch_bounds__(THREADS, 2)
void k_all(const float* __restrict__ weight, const float* __restrict__ bias,
           const float* __restrict__ hiddens, const float* __restrict__ nl,
           const void* __restrict__ targets, const void* __restrict__ samples,
           float* __restrict__ out, int N) {
    extern __shared__ __align__(16) char smem[];
    const int tid = threadIdx.x, w = tid >> 5, lane = tid & 31;
    const int row0 = blockIdx.x << 7;             // 128 rows per CTA
    const uint32_t sb = smem_u32(smem);
    float* cbE  = (float*)(smem + OFF_CBE);
    int*   tIdx = (int*)(smem + OFF_TIDX);
    float* tl   = (float*)(smem + OFF_TL);
    float* rs   = (float*)(smem + OFF_RS);
    float* red  = (float*)(smem + OFF_RED);
    float* wrd  = (float*)(smem + OFF_WRD);
    int*   last = (int*)(smem + OFF_LAST);

    const int is64_t = detect64(targets, lane);   // warp-uniform
    const int is64_s = detect64(samples, lane);

    // ---------- Phase 1: one max-MLP load burst, one barrier ----------
    if (tid < 128) {
        long long t = is64_t ? ((const long long*)targets)[row0 + tid]
                             : (long long)((const int*)targets)[row0 + tid];
        tIdx[tid] = (int)t;
    }
    // A fill: 128 rows fp32 hiddens -> e4m3 padded image (4B per float4 chunk).
#pragma unroll
    for (int it = 0; it < 16; it++) {
        int i = tid + it * THREADS;               // 4096 float4 chunks
        int r = i >> 5, c4 = i & 31;
        float4 v = ((const float4*)hiddens)[((size_t)(row0 + r)) * 32 + c4];
        unsigned u = (unsigned)pk8(v.x, v.y) | ((unsigned)pk8(v.z, v.w) << 16);
        *(unsigned*)(smem + OFF_A + r * ROWB + c4 * 4) = u;
    }
    // B fill: gather sample weight rows, scale x16 -> e4m3 padded image.
#pragma unroll
    for (int it = 0; it < 16; it++) {
        int i = tid + it * THREADS;               // 4096 chunks of 8 elems
        int n = i >> 4, c = i & 15;
        long long s = is64_s ? ((const long long*)samples)[n]
                             : (long long)((const int*)samples)[n];
        const float4* wr = (const float4*)(weight + (size_t)s * HD);
        float4 a = wr[c * 2], b = wr[c * 2 + 1];
        unsigned u0 = (unsigned)pk8(16.f * a.x, 16.f * a.y)
                    | ((unsigned)pk8(16.f * a.z, 16.f * a.w) << 16);
        unsigned u1 = (unsigned)pk8(16.f * b.x, 16.f * b.y)
                    | ((unsigned)pk8(16.f * b.z, 16.f * b.w) << 16);
        *(uint2*)(smem + OFF_B + n * ROWB + c * 8) = make_uint2(u0, u1);
    }
    {
        long long s = is64_s ? ((const long long*)samples)[tid]
                             : (long long)((const int*)samples)[tid];
        cbE[tid] = (bias[s] - nl[s] - CSH) * K2E;
    }
    if (tid == 0) *last = 0;
    __syncthreads();

    // ---------- Phase 2: target logits, full fp32 (gmem hiddens + weight) ----
#pragma unroll
    for (int b = 0; b < 2; b++) {
        int tt[8]; float4 wv[8]; float4 hv[8]; float bn_[8];
#pragma unroll
        for (int j = 0; j < 8; j++) tt[j] = tIdx[w * 16 + b * 8 + j];
#pragma unroll
        for (int j = 0; j < 8; j++)
            wv[j] = ((const float4*)weight)[(size_t)tt[j] * 32 + lane];
#pragma unroll
        for (int j = 0; j < 8; j++) {
            int row = row0 + w * 16 + b * 8 + j;
            hv[j] = ((const float4*)hiddens)[(size_t)row * 32 + lane];
        }
#pragma unroll
        for (int j = 0; j < 8; j++) bn_[j] = __ldg(bias + tt[j]) - __ldg(nl + tt[j]);
#pragma unroll
        for (int j = 0; j < 8; j++) {
            float d = hv[j].x * wv[j].x + hv[j].y * wv[j].y
                    + hv[j].z * wv[j].z + hv[j].w * wv[j].w;
#pragma unroll
            for (int o = 16; o; o >>= 1) d += __shfl_xor_sync(0xffffffffu, d, o);
            if (lane == 0) tl[w * 16 + b * 8 + j] = d + bn_[j];
        }
    }
    // tl consumed only after the epilogue barrier below.

    // ---------- Phase 3: two DRAM-free FP8 MMA + sumexp passes ----------
    float cta_part = 0.f;
    const int bm = (w & 1) * 32, bn = (w >> 1) * 64;
#pragma unroll
    for (int t = 0; t < 2; t++) {
        float d[2][8][4];
#pragma unroll
        for (int mf = 0; mf < 2; mf++)
#pragma unroll
            for (int nf = 0; nf < 8; nf++)
#pragma unroll
                for (int q = 0; q < 4; q++) d[mf][nf][q] = 0.f;

        const uint32_t aB = sb + OFF_A + (t * 64 + bm + (lane & 15)) * ROWB
                          + ((lane >> 4) << 4);
        const uint32_t bB = sb + OFF_B + (bn + (lane & 15)) * ROWB
                          + ((lane >> 4) << 4);
        // K=128 e4m3 in 4 steps of k32 (32 bytes per step).
#pragma unroll
        for (int ks = 0; ks < 4; ks++) {
            const uint32_t off = ks * 32;
            uint32_t a[2][4], bb[4][4];
            LDSM4(a[0], aB + off);
            LDSM4(a[1], aB + 16 * ROWB + off);
#pragma unroll
            for (int q = 0; q < 4; q++) LDSM4(bb[q], bB + q * 16 * ROWB + off);
#pragma unroll
            for (int mf = 0; mf < 2; mf++)
#pragma unroll
                for (int nf = 0; nf < 8; nf++)
                    mma_fp8(d[mf][nf], a[mf], bb[nf >> 1][nf & 1],
                            bb[nf >> 1][(nf & 1) + 2]);
        }

        // Epilogue: per-row sum of exp2(K2E16*d + cbE) over this warp's 64 cols.
        const int g = lane >> 2, t4 = lane & 3;
        float2 cbl[8];
#pragma unroll
        for (int nf = 0; nf < 8; nf++)
            cbl[nf] = *(const float2*)&cbE[bn + nf * 8 + t4 * 2];
#pragma unroll
        for (int mf = 0; mf < 2; mf++)
#pragma unroll
            for (int h = 0; h < 2; h++) {
                int row = bm + mf * 16 + h * 8 + g;
                float s = 0.f;
#pragma unroll
                for (int nf = 0; nf < 8; nf++) {
                    s += exp2f(fmaf(d[mf][nf][h * 2],     K2E16, cbl[nf].x));
                    s += exp2f(fmaf(d[mf][nf][h * 2 + 1], K2E16, cbl[nf].y));
                }
                s += __shfl_xor_sync(0xffffffffu, s, 1);
                s += __shfl_xor_sync(0xffffffffu, s, 2);
                if (t4 == 0) rs[row * 4 + (w >> 1)] = s;
            }
        __syncthreads();

        // Merge 4 n-group partials + target column per row; fixed-order reduce.
        if (w < 2) {
            int row = w * 32 + lane;
            float tv = tl[t * 64 + row];
            float S = rs[row * 4] + rs[row * 4 + 1] + rs[row * 4 + 2] + rs[row * 4 + 3]
                    + exp2f(fmaf(tv, K2E, -TC));
            float res = tv - CSH - 0.5f * logf(S);
#pragma unroll
            for (int o = 16; o; o >>= 1) res += __shfl_xor_sync(0xffffffffu, res, o);
            if (lane == 0) wrd[w] = res;
        }
        __syncthreads();
        if (tid == 0) cta_part += wrd[0] + wrd[1];
        // tid0's read is ordered before the next pass's wrd write by the next
        // epilogue/merge barriers in which tid0 participates.
    }

    // ---------- completion counter + deterministic final reduction ----------
    if (tid == 0) {
        g_partials[blockIdx.x] = cta_part;
        __threadfence();
        unsigned prev = atomicAdd(&g_done, 1u);
        *last = (prev == GRID - 1) ? 1 : 0;
    }
    __syncthreads();
    if (*last) {
        __threadfence();
        red[tid] = g_partials[tid];
        __syncthreads();
#pragma unroll
        for (int s = 128; s > 0; s >>= 1) {
            if (tid < s) red[tid] += red[tid + s];
            __syncthreads();
        }
        if (tid == 0) { out[0] = -red[0] / (float)N; g_done = 0u; }
    }
}

extern "C" void kernel_launch(void* const* d_in, const int* in_sizes, int n_in,
                              void* d_out, int out_size) {
    const float* weight  = (const float*)d_in[0];
    const float* bias    = (const float*)d_in[1];
    const float* hiddens = (const float*)d_in[2];
    const float* nl      = (const float*)d_in[3];
    const void*  targets = d_in[4];
    const void*  samples = d_in[5];
    (void)n_in; (void)out_size;

    const int N = in_sizes[4];          // 32768 -> 256 CTAs x 128 rows

    cudaFuncSetAttribute(k_all, cudaFuncAttributeMaxDynamicSharedMemorySize, SMEM_TOTAL);

    k_all<<<N / 128, THREADS, SMEM_TOTAL>>>(weight, bias, hiddens, nl, targets, samples,
                                            (float*)d_out, N);
}